// round 1
// baseline (speedup 1.0000x reference)
#include <cuda_runtime.h>
#include <cstddef>

#define D_MODEL  1024
#define D_STATE  16
#define D_CONV   4
#define D_INNER  2048
#define DT_RANK  64
#define BATCH    4
#define SEQ      2048
#define MROWS    (BATCH*SEQ)      // 8192
#define DBL_W    (DT_RANK + 2*D_STATE)   // 96

// Scratch (static device allocations are allowed)
__device__ float g_xz[(size_t)MROWS * 2 * D_INNER];     // 134 MB
__device__ float g_xconv[(size_t)MROWS * D_INNER];      // 67 MB
__device__ float g_dbl[(size_t)MROWS * DBL_W];          // 3 MB
__device__ float g_dt[(size_t)MROWS * D_INNER];         // 67 MB
__device__ float g_y[(size_t)MROWS * D_INNER];          // 67 MB

enum { EP_NONE = 0, EP_SOFTPLUS_BIAS = 1 };

// C[M,N] = A[M,K] * B[N,K]^T  (both K-major, "NT"), optional epilogue.
// 128x128 tile, BK=8, 256 threads, 8x8 microtile.
__global__ __launch_bounds__(256, 2)
void sgemm_nt(const float* __restrict__ A, const float* __restrict__ B,
              const float* __restrict__ bias, float* __restrict__ C,
              int M, int N, int K, int lda, int ldb, int ldc, int ep)
{
    __shared__ float As[8][128];
    __shared__ float Bs[8][128];

    const int tid  = threadIdx.x;
    const int ty   = tid >> 4;      // 0..15
    const int tx   = tid & 15;      // 0..15
    const int lrow = tid >> 1;      // 0..127
    const int lseg = tid & 1;       // 0..1

    const int rowBase = blockIdx.y * 128;
    const int colBase = blockIdx.x * 128;

    float acc[8][8];
#pragma unroll
    for (int i = 0; i < 8; i++)
#pragma unroll
        for (int j = 0; j < 8; j++) acc[i][j] = 0.f;

    const bool aOk = (rowBase + lrow) < M;
    const bool bOk = (colBase + lrow) < N;
    const float* Aptr = A + (size_t)(rowBase + lrow) * lda + lseg * 4;
    const float* Bptr = B + (size_t)(colBase + lrow) * ldb + lseg * 4;

    for (int kt = 0; kt < K; kt += 8) {
        float4 av = aOk ? *(const float4*)(Aptr + kt) : make_float4(0.f,0.f,0.f,0.f);
        float4 bv = bOk ? *(const float4*)(Bptr + kt) : make_float4(0.f,0.f,0.f,0.f);
        As[lseg*4+0][lrow] = av.x; As[lseg*4+1][lrow] = av.y;
        As[lseg*4+2][lrow] = av.z; As[lseg*4+3][lrow] = av.w;
        Bs[lseg*4+0][lrow] = bv.x; Bs[lseg*4+1][lrow] = bv.y;
        Bs[lseg*4+2][lrow] = bv.z; Bs[lseg*4+3][lrow] = bv.w;
        __syncthreads();

#pragma unroll
        for (int k = 0; k < 8; k++) {
            float ra[8], rb[8];
#pragma unroll
            for (int i = 0; i < 8; i++) ra[i] = As[k][ty*8 + i];
#pragma unroll
            for (int j = 0; j < 8; j++) rb[j] = Bs[k][tx*8 + j];
#pragma unroll
            for (int i = 0; i < 8; i++)
#pragma unroll
                for (int j = 0; j < 8; j++)
                    acc[i][j] = fmaf(ra[i], rb[j], acc[i][j]);
        }
        __syncthreads();
    }

#pragma unroll
    for (int i = 0; i < 8; i++) {
        int r = rowBase + ty*8 + i;
        if (r >= M) continue;
#pragma unroll
        for (int j = 0; j < 8; j++) {
            int c = colBase + tx*8 + j;
            if (c >= N) continue;
            float v = acc[i][j];
            if (ep == EP_SOFTPLUS_BIAS) {
                v += bias[c];
                v = (v > 20.f) ? v : log1pf(expf(v));
            }
            C[(size_t)r * ldc + c] = v;
        }
    }
}

// Causal depthwise conv (k=4) over time + SiLU. x_in lives in g_xz cols [0, D_INNER).
__global__ void conv_silu_kernel(const float* __restrict__ xz,
                                 const float* __restrict__ w,
                                 float* __restrict__ xc)
{
    int idx = blockIdx.x * blockDim.x + threadIdx.x;
    if (idx >= MROWS * D_INNER) return;
    int d   = idx & (D_INNER - 1);
    int row = idx >> 11;                 // /D_INNER
    int t   = row & (SEQ - 1);

    float s = 0.f;
#pragma unroll
    for (int k = 0; k < D_CONV; k++) {
        int tt = t - (D_CONV - 1) + k;
        if (tt >= 0)
            s = fmaf(w[d*D_CONV + k],
                     xz[(size_t)(row - (D_CONV - 1) + k) * (2*D_INNER) + d], s);
    }
    float sig = 1.f / (1.f + __expf(-s));
    xc[idx] = s * sig;
}

// Selective scan: 16 lanes per (b,d) channel, one state per lane.
// Fuses D-skip and SiLU(z) gating; writes y_final.
__global__ __launch_bounds__(256)
void scan_kernel(const float* __restrict__ dt, const float* __restrict__ xc,
                 const float* __restrict__ xz, const float* __restrict__ dbl,
                 const float* __restrict__ A_log, const float* __restrict__ Dp,
                 float* __restrict__ y)
{
    const int tid = threadIdx.x;
    const int ch  = blockIdx.x * (blockDim.x >> 4) + (tid >> 4);
    const int n   = tid & 15;
    const int b   = ch / D_INNER;
    const int d   = ch & (D_INNER - 1);

    const float Aval = -expf(A_log[d * D_STATE + n]);
    const float Dval = Dp[d];

    float h = 0.f;
    size_t row = (size_t)b * SEQ;
    for (int t = 0; t < SEQ; t++, row++) {
        const float dtv = dt[row * D_INNER + d];
        const float xv  = xc[row * D_INNER + d];
        const float Bv  = dbl[row * DBL_W + DT_RANK + n];
        const float Cv  = dbl[row * DBL_W + DT_RANK + D_STATE + n];

        h = fmaf(h, __expf(dtv * Aval), dtv * Bv * xv);
        float p = h * Cv;
        p += __shfl_xor_sync(0xffffffffu, p, 1);
        p += __shfl_xor_sync(0xffffffffu, p, 2);
        p += __shfl_xor_sync(0xffffffffu, p, 4);
        p += __shfl_xor_sync(0xffffffffu, p, 8);

        if (n == 0) {
            float zv  = xz[row * (2*D_INNER) + D_INNER + d];
            float ys  = p + Dval * xv;
            float sig = 1.f / (1.f + __expf(-zv));
            y[row * D_INNER + d] = ys * (zv * sig);
        }
    }
}

extern "C" void kernel_launch(void* const* d_in, const int* in_sizes, int n_in,
                              void* d_out, int out_size)
{
    const float* x      = (const float*)d_in[0];
    const float* W_in   = (const float*)d_in[1];
    const float* conv_w = (const float*)d_in[2];
    const float* W_x    = (const float*)d_in[3];
    const float* W_dt   = (const float*)d_in[4];
    const float* b_dt   = (const float*)d_in[5];
    const float* A_log  = (const float*)d_in[6];
    const float* Dp     = (const float*)d_in[7];
    const float* W_out  = (const float*)d_in[8];
    float* out = (float*)d_out;

    float *xz, *xc, *dbl, *dtp, *y;
    cudaGetSymbolAddress((void**)&xz,  g_xz);
    cudaGetSymbolAddress((void**)&xc,  g_xconv);
    cudaGetSymbolAddress((void**)&dbl, g_dbl);
    cudaGetSymbolAddress((void**)&dtp, g_dt);
    cudaGetSymbolAddress((void**)&y,   g_y);

    // 1) xz = x @ W_in^T : (8192 x 4096), K=1024
    sgemm_nt<<<dim3(4096/128, MROWS/128), 256>>>(x, W_in, nullptr, xz,
        MROWS, 2*D_INNER, D_MODEL, D_MODEL, D_MODEL, 2*D_INNER, EP_NONE);

    // 2) depthwise causal conv + SiLU
    conv_silu_kernel<<<(MROWS*D_INNER + 255)/256, 256>>>(xz, conv_w, xc);

    // 3) dbl = x_conv @ W_x^T : (8192 x 96), K=2048
    sgemm_nt<<<dim3(1, MROWS/128), 256>>>(xc, W_x, nullptr, dbl,
        MROWS, DBL_W, D_INNER, D_INNER, D_INNER, DBL_W, EP_NONE);

    // 4) dt = softplus(dbl[:, :64] @ W_dt^T + b_dt) : (8192 x 2048), K=64
    sgemm_nt<<<dim3(D_INNER/128, MROWS/128), 256>>>(dbl, W_dt, b_dt, dtp,
        MROWS, D_INNER, DT_RANK, DBL_W, DT_RANK, D_INNER, EP_SOFTPLUS_BIAS);

    // 5) selective scan + skip + gating -> y_final
    scan_kernel<<<(BATCH*D_INNER)/16, 256>>>(dtp, xc, xz, dbl, A_log, Dp, y);

    // 6) out = y_final @ W_out^T : (8192 x 1024), K=2048
    sgemm_nt<<<dim3(D_MODEL/128, MROWS/128), 256>>>(y, W_out, nullptr, out,
        MROWS, D_MODEL, D_INNER, D_INNER, D_INNER, D_MODEL, EP_NONE);
}

// round 5
// speedup vs baseline: 2.7258x; 2.7258x over previous
#include <cuda_runtime.h>
#include <cuda_bf16.h>
#include <cstdint>
#include <cstddef>

#define D_MODEL  1024
#define D_STATE  16
#define D_CONV   4
#define D_INNER  2048
#define DT_RANK  64
#define BATCH    4
#define SEQ      2048
#define MROWS    (BATCH*SEQ)             // 8192
#define DBL_W    (DT_RANK + 2*D_STATE)   // 96

// ---------------- scratch ----------------
__device__ float g_xz[(size_t)MROWS * 2 * D_INNER];
__device__ float g_xconv[(size_t)MROWS * D_INNER];
__device__ float g_dbl[(size_t)MROWS * DBL_W];
__device__ float g_dt[(size_t)MROWS * D_INNER];

__device__ __nv_bfloat16 g_xhi[(size_t)MROWS * D_MODEL];
__device__ __nv_bfloat16 g_xlo[(size_t)MROWS * D_MODEL];
__device__ __nv_bfloat16 g_wihi[(size_t)(2*D_INNER) * D_MODEL];
__device__ __nv_bfloat16 g_wilo[(size_t)(2*D_INNER) * D_MODEL];
__device__ __nv_bfloat16 g_yhi[(size_t)MROWS * D_INNER];
__device__ __nv_bfloat16 g_ylo[(size_t)MROWS * D_INNER];
__device__ __nv_bfloat16 g_wohi[(size_t)D_MODEL * D_INNER];
__device__ __nv_bfloat16 g_wolo[(size_t)D_MODEL * D_INNER];

// ---------------- PTX helpers (sm_80-compatible only) ----------------
__device__ __forceinline__ uint32_t smem_u32(const void* p) {
    uint32_t a;
    asm("{ .reg .u64 t; cvta.to.shared.u64 t, %1; cvt.u32.u64 %0, t; }"
        : "=r"(a) : "l"(p));
    return a;
}
__device__ __forceinline__ void cp16(uint32_t saddr, const void* gaddr) {
    asm volatile("cp.async.cg.shared.global [%0], [%1], 16;" :: "r"(saddr), "l"(gaddr));
}
#define CP_COMMIT() asm volatile("cp.async.commit_group;" ::: "memory")
#define CP_WAIT(n)  asm volatile("cp.async.wait_group %0;" :: "n"(n) : "memory")

__device__ __forceinline__ void ldsm4(uint32_t* r, uint32_t addr) {
    asm volatile("ldmatrix.sync.aligned.m8n8.x4.shared.b16 {%0,%1,%2,%3}, [%4];"
        : "=r"(r[0]), "=r"(r[1]), "=r"(r[2]), "=r"(r[3]) : "r"(addr));
}
__device__ __forceinline__ void mma16816(float* c, const uint32_t* a, const uint32_t* b) {
    asm volatile("mma.sync.aligned.m16n8k16.row.col.f32.bf16.bf16.f32 "
        "{%0,%1,%2,%3}, {%4,%5,%6,%7}, {%8,%9}, {%0,%1,%2,%3};"
        : "+f"(c[0]), "+f"(c[1]), "+f"(c[2]), "+f"(c[3])
        : "r"(a[0]), "r"(a[1]), "r"(a[2]), "r"(a[3]), "r"(b[0]), "r"(b[1]));
}

// ---------------- bf16x3 tensor-core GEMM via mma.sync ----------------
// C[M,N] = Ahi*Bhi^T + Ahi*Blo^T + Alo*Bhi^T  (A:[M,K], B:[N,K], K-major bf16)
// CTA 128x128, BK=32, 8 warps (2x4), warp tile 64x32, 3-stage cp.async pipeline.
#define APITCH 80                         // bytes per 32-col bf16 row (64B + 16B pad)
#define TILE_B (128*APITCH)               // 10240
#define STAGE_B (4*TILE_B)                // 40960 : Ahi|Alo|Bhi|Blo
#define STAGES 3
#define MMA_SMEM (STAGES*STAGE_B)         // 122880

__global__ __launch_bounds__(256, 1)
void gemm_bf16x3_mma(const __nv_bfloat16* __restrict__ Ahi, const __nv_bfloat16* __restrict__ Alo,
                     const __nv_bfloat16* __restrict__ Bhi, const __nv_bfloat16* __restrict__ Blo,
                     float* __restrict__ C, int K, int ldc)
{
    extern __shared__ char smem[];
    const uint32_t sb = smem_u32(smem);
    const int tid = threadIdx.x;
    const int lane = tid & 31;
    const int wid = tid >> 5;
    const int wr = wid >> 2;                // 0..1
    const int wc = wid & 3;                 // 0..3
    const int rowBase = blockIdx.y * 128;
    const int colBase = blockIdx.x * 128;

    float acc[4][4][4];
#pragma unroll
    for (int m = 0; m < 4; m++)
#pragma unroll
        for (int n = 0; n < 4; n++)
#pragma unroll
            for (int q = 0; q < 4; q++) acc[m][n][q] = 0.f;

    auto load_stage = [&](int kc, int s) {
        const uint32_t stb = sb + s * STAGE_B;
#pragma unroll
        for (int t = 0; t < 4; t++) {
            const __nv_bfloat16* src = (t == 0) ? Ahi : (t == 1) ? Alo : (t == 2) ? Bhi : Blo;
            const int gbase = (t < 2) ? rowBase : colBase;
            const uint32_t stile = stb + t * TILE_B;
#pragma unroll
            for (int j = 0; j < 2; j++) {
                int c = tid + j * 256;          // 0..511
                int row = c >> 2, seg = c & 3;
                cp16(stile + row * APITCH + seg * 16,
                     src + (size_t)(gbase + row) * K + kc * 32 + seg * 8);
            }
        }
        CP_COMMIT();
    };

    for (int s = 0; s < STAGES - 1; s++) load_stage(s, s);

    const int nch = K / 32;
    // precomputed ldmatrix lane offsets
    const uint32_t aoff = (uint32_t)((wr * 64 + (lane & 15)) * APITCH + (lane >> 4) * 16);
    const uint32_t boff = (uint32_t)((wc * 32 + (lane & 7) + ((lane >> 4) & 1) * 8) * APITCH
                                     + ((lane >> 3) & 1) * 16);

    for (int i = 0; i < nch; i++) {
        CP_WAIT(STAGES - 2);
        __syncthreads();
        if (i + STAGES - 1 < nch) load_stage(i + STAGES - 1, (i + STAGES - 1) % STAGES);
        else CP_COMMIT();

        const uint32_t stb = sb + (i % STAGES) * STAGE_B;
#pragma unroll
        for (int k16 = 0; k16 < 2; k16++) {
            uint32_t ah[4][4], al[4][4], bh[2][4], bl[2][4];
#pragma unroll
            for (int m = 0; m < 4; m++) {
                uint32_t ad = stb + aoff + m * 16 * APITCH + k16 * 32;
                ldsm4(ah[m], ad);
                ldsm4(al[m], ad + TILE_B);
            }
#pragma unroll
            for (int p = 0; p < 2; p++) {
                uint32_t bd = stb + 2 * TILE_B + boff + p * 16 * APITCH + k16 * 32;
                ldsm4(bh[p], bd);
                ldsm4(bl[p], bd + TILE_B);
            }
#pragma unroll
            for (int m = 0; m < 4; m++)
#pragma unroll
                for (int n = 0; n < 4; n++) {
                    const uint32_t* fh = &bh[n >> 1][(n & 1) * 2];
                    const uint32_t* fl = &bl[n >> 1][(n & 1) * 2];
                    mma16816(acc[m][n], ah[m], fh);
                    mma16816(acc[m][n], ah[m], fl);
                    mma16816(acc[m][n], al[m], fh);
                }
        }
    }

    // epilogue
    const int row0 = rowBase + wr * 64 + (lane >> 2);
    const int col0 = colBase + wc * 32 + (lane & 3) * 2;
#pragma unroll
    for (int m = 0; m < 4; m++)
#pragma unroll
        for (int n = 0; n < 4; n++) {
            int r = row0 + m * 16;
            int cc = col0 + n * 8;
            *(float2*)&C[(size_t)r * ldc + cc]       = make_float2(acc[m][n][0], acc[m][n][1]);
            *(float2*)&C[(size_t)(r + 8) * ldc + cc] = make_float2(acc[m][n][2], acc[m][n][3]);
        }
}

// ---------------- fp32 -> bf16 hi/lo split ----------------
__global__ void split_bf16(const float* __restrict__ src, __nv_bfloat16* __restrict__ hi,
                           __nv_bfloat16* __restrict__ lo, int n)
{
    int i = blockIdx.x * blockDim.x + threadIdx.x;
    if (i >= n) return;
    float v = src[i];
    __nv_bfloat16 h = __float2bfloat16(v);
    hi[i] = h;
    lo[i] = __float2bfloat16(v - __bfloat162float(h));
}

// ---------------- scalar SGEMM (small GEMMs) ----------------
enum { EP_NONE = 0, EP_SOFTPLUS_BIAS = 1 };
__global__ __launch_bounds__(256, 2)
void sgemm_nt(const float* __restrict__ A, const float* __restrict__ B,
              const float* __restrict__ bias, float* __restrict__ C,
              int M, int N, int K, int lda, int ldb, int ldc, int ep)
{
    __shared__ float As[8][128];
    __shared__ float Bs[8][128];
    const int tid = threadIdx.x;
    const int ty = tid >> 4, tx = tid & 15;
    const int lrow = tid >> 1, lseg = tid & 1;
    const int rowBase = blockIdx.y * 128, colBase = blockIdx.x * 128;

    float acc[8][8];
#pragma unroll
    for (int i = 0; i < 8; i++)
#pragma unroll
        for (int j = 0; j < 8; j++) acc[i][j] = 0.f;

    const bool aOk = (rowBase + lrow) < M;
    const bool bOk = (colBase + lrow) < N;
    const float* Aptr = A + (size_t)(rowBase + lrow) * lda + lseg * 4;
    const float* Bptr = B + (size_t)(colBase + lrow) * ldb + lseg * 4;

    for (int kt = 0; kt < K; kt += 8) {
        float4 av = aOk ? *(const float4*)(Aptr + kt) : make_float4(0.f, 0.f, 0.f, 0.f);
        float4 bv = bOk ? *(const float4*)(Bptr + kt) : make_float4(0.f, 0.f, 0.f, 0.f);
        As[lseg * 4 + 0][lrow] = av.x; As[lseg * 4 + 1][lrow] = av.y;
        As[lseg * 4 + 2][lrow] = av.z; As[lseg * 4 + 3][lrow] = av.w;
        Bs[lseg * 4 + 0][lrow] = bv.x; Bs[lseg * 4 + 1][lrow] = bv.y;
        Bs[lseg * 4 + 2][lrow] = bv.z; Bs[lseg * 4 + 3][lrow] = bv.w;
        __syncthreads();
#pragma unroll
        for (int k = 0; k < 8; k++) {
            float ra[8], rb[8];
#pragma unroll
            for (int i = 0; i < 8; i++) ra[i] = As[k][ty * 8 + i];
#pragma unroll
            for (int j = 0; j < 8; j++) rb[j] = Bs[k][tx * 8 + j];
#pragma unroll
            for (int i = 0; i < 8; i++)
#pragma unroll
                for (int j = 0; j < 8; j++)
                    acc[i][j] = fmaf(ra[i], rb[j], acc[i][j]);
        }
        __syncthreads();
    }
#pragma unroll
    for (int i = 0; i < 8; i++) {
        int r = rowBase + ty * 8 + i;
        if (r >= M) continue;
#pragma unroll
        for (int j = 0; j < 8; j++) {
            int c = colBase + tx * 8 + j;
            if (c >= N) continue;
            float v = acc[i][j];
            if (ep == EP_SOFTPLUS_BIAS) {
                v += bias[c];
                v = (v > 20.f) ? v : log1pf(expf(v));
            }
            C[(size_t)r * ldc + c] = v;
        }
    }
}

// ---------------- depthwise causal conv (k=4) + SiLU ----------------
__global__ void conv_silu_kernel(const float* __restrict__ xz,
                                 const float* __restrict__ w,
                                 float* __restrict__ xc)
{
    int idx = blockIdx.x * blockDim.x + threadIdx.x;
    if (idx >= MROWS * D_INNER) return;
    int d = idx & (D_INNER - 1);
    int row = idx >> 11;
    int t = row & (SEQ - 1);
    float s = 0.f;
#pragma unroll
    for (int k = 0; k < D_CONV; k++) {
        int tt = t - (D_CONV - 1) + k;
        if (tt >= 0)
            s = fmaf(w[d * D_CONV + k],
                     xz[(size_t)(row - (D_CONV - 1) + k) * (2 * D_INNER) + d], s);
    }
    float sig = 1.f / (1.f + __expf(-s));
    xc[idx] = s * sig;
}

// ---------------- selective scan (coalesced, SMEM chunked) ----------------
#define SCHUNK 64
__global__ __launch_bounds__(256)
void scan_kernel(const float* __restrict__ dt, const float* __restrict__ xc,
                 const float* __restrict__ xz, const float* __restrict__ dblp,
                 const float* __restrict__ A_log, const float* __restrict__ Dp,
                 __nv_bfloat16* __restrict__ yhi, __nv_bfloat16* __restrict__ ylo)
{
    __shared__ float s_dt[SCHUNK][16];
    __shared__ float s_xc[SCHUNK][16];
    __shared__ float s_z[SCHUNK][16];
    __shared__ float s_B[SCHUNK][16];
    __shared__ float s_C[SCHUNK][16];
    __shared__ float s_y[SCHUNK][16];

    const int tid = threadIdx.x;
    const int g = tid >> 4;
    const int n = tid & 15;
    const int b = blockIdx.x >> 7;
    const int dblk = (blockIdx.x & 127) * 16;
    const int d = dblk + g;

    const float Aval = -expf(A_log[d * D_STATE + n]);
    const float Dval = Dp[d];

    float h = 0.f;
    for (int c = 0; c < SEQ / SCHUNK; c++) {
        const size_t rbase = (size_t)b * SEQ + c * SCHUNK;
        for (int idx = tid; idx < SCHUNK * 16; idx += 256) {
            int t = idx >> 4, j = idx & 15;
            size_t row = rbase + t;
            s_dt[t][j] = dt[row * D_INNER + dblk + j];
            s_xc[t][j] = xc[row * D_INNER + dblk + j];
            s_z[t][j]  = xz[row * (2 * D_INNER) + D_INNER + dblk + j];
            s_B[t][j]  = dblp[row * DBL_W + DT_RANK + j];
            s_C[t][j]  = dblp[row * DBL_W + DT_RANK + D_STATE + j];
        }
        __syncthreads();
#pragma unroll 4
        for (int t = 0; t < SCHUNK; t++) {
            float dtv = s_dt[t][g];
            float xv  = s_xc[t][g];
            float Bv  = s_B[t][n];
            float Cv  = s_C[t][n];
            h = fmaf(h, __expf(dtv * Aval), dtv * Bv * xv);
            float p = h * Cv;
            p += __shfl_xor_sync(0xffffffffu, p, 1);
            p += __shfl_xor_sync(0xffffffffu, p, 2);
            p += __shfl_xor_sync(0xffffffffu, p, 4);
            p += __shfl_xor_sync(0xffffffffu, p, 8);
            if (n == 0) s_y[t][g] = p + Dval * xv;
        }
        __syncthreads();
        for (int idx = tid; idx < SCHUNK * 16; idx += 256) {
            int t = idx >> 4, j = idx & 15;
            size_t row = rbase + t;
            float zv = s_z[t][j];
            float sig = 1.f / (1.f + __expf(-zv));
            float v = s_y[t][j] * (zv * sig);
            __nv_bfloat16 hv = __float2bfloat16(v);
            yhi[row * D_INNER + dblk + j] = hv;
            ylo[row * D_INNER + dblk + j] = __float2bfloat16(v - __bfloat162float(hv));
        }
        __syncthreads();
    }
}

// ---------------- launcher ----------------
extern "C" void kernel_launch(void* const* d_in, const int* in_sizes, int n_in,
                              void* d_out, int out_size)
{
    const float* x      = (const float*)d_in[0];
    const float* W_in   = (const float*)d_in[1];
    const float* conv_w = (const float*)d_in[2];
    const float* W_x    = (const float*)d_in[3];
    const float* W_dt   = (const float*)d_in[4];
    const float* b_dt   = (const float*)d_in[5];
    const float* A_log  = (const float*)d_in[6];
    const float* Dp     = (const float*)d_in[7];
    const float* W_out  = (const float*)d_in[8];
    float* out = (float*)d_out;

    float *xz, *xc, *dblp, *dtp;
    cudaGetSymbolAddress((void**)&xz, g_xz);
    cudaGetSymbolAddress((void**)&xc, g_xconv);
    cudaGetSymbolAddress((void**)&dblp, g_dbl);
    cudaGetSymbolAddress((void**)&dtp, g_dt);
    __nv_bfloat16 *xhi, *xlo, *wihi, *wilo, *yhi, *ylo, *wohi, *wolo;
    cudaGetSymbolAddress((void**)&xhi, g_xhi);
    cudaGetSymbolAddress((void**)&xlo, g_xlo);
    cudaGetSymbolAddress((void**)&wihi, g_wihi);
    cudaGetSymbolAddress((void**)&wilo, g_wilo);
    cudaGetSymbolAddress((void**)&yhi, g_yhi);
    cudaGetSymbolAddress((void**)&ylo, g_ylo);
    cudaGetSymbolAddress((void**)&wohi, g_wohi);
    cudaGetSymbolAddress((void**)&wolo, g_wolo);

    cudaFuncSetAttribute(gemm_bf16x3_mma, cudaFuncAttributeMaxDynamicSharedMemorySize, MMA_SMEM);

    // splits for GEMM 1
    split_bf16<<<(MROWS * D_MODEL + 255) / 256, 256>>>(x, xhi, xlo, MROWS * D_MODEL);
    split_bf16<<<(2 * D_INNER * D_MODEL + 255) / 256, 256>>>(W_in, wihi, wilo, 2 * D_INNER * D_MODEL);

    // 1) xz = x @ W_in^T  (8192 x 4096, K=1024)  tensor cores
    gemm_bf16x3_mma<<<dim3(4096 / 128, MROWS / 128), 256, MMA_SMEM>>>(
        xhi, xlo, wihi, wilo, xz, D_MODEL, 2 * D_INNER);

    // 2) depthwise causal conv + SiLU
    conv_silu_kernel<<<(MROWS * D_INNER + 255) / 256, 256>>>(xz, conv_w, xc);

    // 3) dbl = x_conv @ W_x^T  (8192 x 96, K=2048)
    sgemm_nt<<<dim3(1, MROWS / 128), 256>>>(xc, W_x, nullptr, dblp,
        MROWS, DBL_W, D_INNER, D_INNER, D_INNER, DBL_W, EP_NONE);

    // 4) dt = softplus(dbl[:, :64] @ W_dt^T + b_dt)  (8192 x 2048, K=64)
    sgemm_nt<<<dim3(D_INNER / 128, MROWS / 128), 256>>>(dblp, W_dt, b_dt, dtp,
        MROWS, D_INNER, DT_RANK, DBL_W, DT_RANK, D_INNER, EP_SOFTPLUS_BIAS);

    // 5) selective scan + skip + gating -> yhi/ylo (bf16 split fused)
    scan_kernel<<<BATCH * (D_INNER / 16), 256>>>(dtp, xc, xz, dblp, A_log, Dp, yhi, ylo);

    // split W_out
    split_bf16<<<(D_MODEL * D_INNER + 255) / 256, 256>>>(W_out, wohi, wolo, D_MODEL * D_INNER);

    // 6) out = y @ W_out^T  (8192 x 1024, K=2048)  tensor cores
    gemm_bf16x3_mma<<<dim3(D_MODEL / 128, MROWS / 128), 256, MMA_SMEM>>>(
        yhi, ylo, wohi, wolo, out, D_INNER, D_MODEL);
}

// round 6
// speedup vs baseline: 3.1675x; 1.1620x over previous
#include <cuda_runtime.h>
#include <cuda_bf16.h>
#include <cstdint>
#include <cstddef>

#define D_MODEL  1024
#define D_STATE  16
#define D_CONV   4
#define D_INNER  2048
#define DT_RANK  64
#define BATCH    4
#define SEQ      2048
#define MROWS    (BATCH*SEQ)             // 8192
#define DBL_W    (DT_RANK + 2*D_STATE)   // 96

// ---------------- scratch ----------------
__device__ float g_xz[(size_t)MROWS * 2 * D_INNER];
__device__ float g_xconv[(size_t)MROWS * D_INNER];
__device__ float g_dbl[(size_t)MROWS * DBL_W];
__device__ float g_dt[(size_t)MROWS * D_INNER];

__device__ __nv_bfloat16 g_xhi[(size_t)MROWS * D_MODEL];
__device__ __nv_bfloat16 g_xlo[(size_t)MROWS * D_MODEL];
__device__ __nv_bfloat16 g_wihi[(size_t)(2*D_INNER) * D_MODEL];
__device__ __nv_bfloat16 g_wilo[(size_t)(2*D_INNER) * D_MODEL];
__device__ __nv_bfloat16 g_yhi[(size_t)MROWS * D_INNER];
__device__ __nv_bfloat16 g_ylo[(size_t)MROWS * D_INNER];
__device__ __nv_bfloat16 g_wohi[(size_t)D_MODEL * D_INNER];
__device__ __nv_bfloat16 g_wolo[(size_t)D_MODEL * D_INNER];
// new: conv output split, padded W_x split, dbl[:, :64] split, W_dt split
__device__ __nv_bfloat16 g_xchi[(size_t)MROWS * D_INNER];
__device__ __nv_bfloat16 g_xclo[(size_t)MROWS * D_INNER];
__device__ __nv_bfloat16 g_wxhi[(size_t)128 * D_INNER];
__device__ __nv_bfloat16 g_wxlo[(size_t)128 * D_INNER];
__device__ __nv_bfloat16 g_d4hi[(size_t)MROWS * DT_RANK];
__device__ __nv_bfloat16 g_d4lo[(size_t)MROWS * DT_RANK];
__device__ __nv_bfloat16 g_wdthi[(size_t)D_INNER * DT_RANK];
__device__ __nv_bfloat16 g_wdtlo[(size_t)D_INNER * DT_RANK];

// ---------------- PTX helpers (sm_80-compatible only) ----------------
__device__ __forceinline__ uint32_t smem_u32(const void* p) {
    uint32_t a;
    asm("{ .reg .u64 t; cvta.to.shared.u64 t, %1; cvt.u32.u64 %0, t; }"
        : "=r"(a) : "l"(p));
    return a;
}
__device__ __forceinline__ void cp16(uint32_t saddr, const void* gaddr) {
    asm volatile("cp.async.cg.shared.global [%0], [%1], 16;" :: "r"(saddr), "l"(gaddr));
}
#define CP_COMMIT() asm volatile("cp.async.commit_group;" ::: "memory")
#define CP_WAIT(n)  asm volatile("cp.async.wait_group %0;" :: "n"(n) : "memory")

__device__ __forceinline__ void ldsm4(uint32_t* r, uint32_t addr) {
    asm volatile("ldmatrix.sync.aligned.m8n8.x4.shared.b16 {%0,%1,%2,%3}, [%4];"
        : "=r"(r[0]), "=r"(r[1]), "=r"(r[2]), "=r"(r[3]) : "r"(addr));
}
__device__ __forceinline__ void mma16816(float* c, const uint32_t* a, const uint32_t* b) {
    asm volatile("mma.sync.aligned.m16n8k16.row.col.f32.bf16.bf16.f32 "
        "{%0,%1,%2,%3}, {%4,%5,%6,%7}, {%8,%9}, {%0,%1,%2,%3};"
        : "+f"(c[0]), "+f"(c[1]), "+f"(c[2]), "+f"(c[3])
        : "r"(a[0]), "r"(a[1]), "r"(a[2]), "r"(a[3]), "r"(b[0]), "r"(b[1]));
}

enum { EP_NONE = 0, EP_SOFTPLUS_BIAS = 1 };

// ---------------- bf16x3 tensor-core GEMM via mma.sync ----------------
// C[M,N] = Ahi*Bhi^T + Ahi*Blo^T + Alo*Bhi^T  (A:[M,K] lda, B:[N,K] ldb, K-major bf16)
// CTA 128x128, BK=32, 8 warps (2x4), warp tile 64x32, 3-stage cp.async pipeline.
// Requirements: M % 128 == 0; B has at least ceil(N/128)*128 valid (zero-padded) rows;
// K % 32 == 0 and K >= 64. Stores guarded by col < N.
#define APITCH 80                         // bytes per 32-col bf16 row (64B + 16B pad)
#define TILE_B (128*APITCH)               // 10240
#define STAGE_B (4*TILE_B)                // 40960 : Ahi|Alo|Bhi|Blo
#define STAGES 3
#define MMA_SMEM (STAGES*STAGE_B)         // 122880

__global__ __launch_bounds__(256, 1)
void gemm_bf16x3_mma(const __nv_bfloat16* __restrict__ Ahi, const __nv_bfloat16* __restrict__ Alo,
                     const __nv_bfloat16* __restrict__ Bhi, const __nv_bfloat16* __restrict__ Blo,
                     const float* __restrict__ bias, float* __restrict__ C,
                     int N, int K, int lda, int ldb, int ldc, int ep)
{
    extern __shared__ char smem[];
    const uint32_t sb = smem_u32(smem);
    const int tid = threadIdx.x;
    const int lane = tid & 31;
    const int wid = tid >> 5;
    const int wr = wid >> 2;                // 0..1
    const int wc = wid & 3;                 // 0..3
    const int rowBase = blockIdx.y * 128;
    const int colBase = blockIdx.x * 128;

    float acc[4][4][4];
#pragma unroll
    for (int m = 0; m < 4; m++)
#pragma unroll
        for (int n = 0; n < 4; n++)
#pragma unroll
            for (int q = 0; q < 4; q++) acc[m][n][q] = 0.f;

    auto load_stage = [&](int kc, int s) {
        const uint32_t stb = sb + s * STAGE_B;
#pragma unroll
        for (int t = 0; t < 4; t++) {
            const __nv_bfloat16* src = (t == 0) ? Ahi : (t == 1) ? Alo : (t == 2) ? Bhi : Blo;
            const int gbase = (t < 2) ? rowBase : colBase;
            const int ld = (t < 2) ? lda : ldb;
            const uint32_t stile = stb + t * TILE_B;
#pragma unroll
            for (int j = 0; j < 2; j++) {
                int c = tid + j * 256;          // 0..511
                int row = c >> 2, seg = c & 3;
                cp16(stile + row * APITCH + seg * 16,
                     src + (size_t)(gbase + row) * ld + kc * 32 + seg * 8);
            }
        }
        CP_COMMIT();
    };

    const int nch = K / 32;
    for (int s = 0; s < STAGES - 1; s++) {
        if (s < nch) load_stage(s, s);
        else CP_COMMIT();
    }

    // precomputed ldmatrix lane offsets
    const uint32_t aoff = (uint32_t)((wr * 64 + (lane & 15)) * APITCH + (lane >> 4) * 16);
    const uint32_t boff = (uint32_t)((wc * 32 + (lane & 7) + ((lane >> 4) & 1) * 8) * APITCH
                                     + ((lane >> 3) & 1) * 16);

    for (int i = 0; i < nch; i++) {
        CP_WAIT(STAGES - 2);
        __syncthreads();
        if (i + STAGES - 1 < nch) load_stage(i + STAGES - 1, (i + STAGES - 1) % STAGES);
        else CP_COMMIT();

        const uint32_t stb = sb + (i % STAGES) * STAGE_B;
#pragma unroll
        for (int k16 = 0; k16 < 2; k16++) {
            uint32_t ah[4][4], al[4][4], bh[2][4], bl[2][4];
#pragma unroll
            for (int m = 0; m < 4; m++) {
                uint32_t ad = stb + aoff + m * 16 * APITCH + k16 * 32;
                ldsm4(ah[m], ad);
                ldsm4(al[m], ad + TILE_B);
            }
#pragma unroll
            for (int p = 0; p < 2; p++) {
                uint32_t bd = stb + 2 * TILE_B + boff + p * 16 * APITCH + k16 * 32;
                ldsm4(bh[p], bd);
                ldsm4(bl[p], bd + TILE_B);
            }
#pragma unroll
            for (int m = 0; m < 4; m++)
#pragma unroll
                for (int n = 0; n < 4; n++) {
                    const uint32_t* fh = &bh[n >> 1][(n & 1) * 2];
                    const uint32_t* fl = &bl[n >> 1][(n & 1) * 2];
                    mma16816(acc[m][n], ah[m], fh);
                    mma16816(acc[m][n], ah[m], fl);
                    mma16816(acc[m][n], al[m], fh);
                }
        }
    }

    // epilogue
    const int row0 = rowBase + wr * 64 + (lane >> 2);
    const int col0 = colBase + wc * 32 + (lane & 3) * 2;
#pragma unroll
    for (int m = 0; m < 4; m++)
#pragma unroll
        for (int n = 0; n < 4; n++) {
            int r = row0 + m * 16;
            int cc = col0 + n * 8;
            if (cc >= N) continue;
            float v0 = acc[m][n][0], v1 = acc[m][n][1];
            float v2 = acc[m][n][2], v3 = acc[m][n][3];
            if (ep == EP_SOFTPLUS_BIAS) {
                float b0 = bias[cc], b1 = bias[cc + 1];
                v0 += b0; v1 += b1; v2 += b0; v3 += b1;
                v0 = (v0 > 20.f) ? v0 : log1pf(expf(v0));
                v1 = (v1 > 20.f) ? v1 : log1pf(expf(v1));
                v2 = (v2 > 20.f) ? v2 : log1pf(expf(v2));
                v3 = (v3 > 20.f) ? v3 : log1pf(expf(v3));
            }
            *(float2*)&C[(size_t)r * ldc + cc]       = make_float2(v0, v1);
            *(float2*)&C[(size_t)(r + 8) * ldc + cc] = make_float2(v2, v3);
        }
}

// ---------------- fp32 -> bf16 hi/lo split ----------------
__global__ void split_bf16(const float* __restrict__ src, __nv_bfloat16* __restrict__ hi,
                           __nv_bfloat16* __restrict__ lo, int n)
{
    int i = blockIdx.x * blockDim.x + threadIdx.x;
    if (i >= n) return;
    float v = src[i];
    __nv_bfloat16 h = __float2bfloat16(v);
    hi[i] = h;
    lo[i] = __float2bfloat16(v - __bfloat162float(h));
}

// split with zero row-padding: src [rows_valid x cols] -> hi/lo [rows_total x cols]
__global__ void split_pad_bf16(const float* __restrict__ src, __nv_bfloat16* __restrict__ hi,
                               __nv_bfloat16* __restrict__ lo, int rows_valid, int rows_total, int cols)
{
    int i = blockIdx.x * blockDim.x + threadIdx.x;
    if (i >= rows_total * cols) return;
    int r = i / cols;
    float v = (r < rows_valid) ? src[i] : 0.f;
    __nv_bfloat16 h = __float2bfloat16(v);
    hi[i] = h;
    lo[i] = __float2bfloat16(v - __bfloat162float(h));
}

// split dbl[:, 0:64] (row stride 96) into compact [MROWS x 64] hi/lo
__global__ void split_dbl64(const float* __restrict__ dbl, __nv_bfloat16* __restrict__ hi,
                            __nv_bfloat16* __restrict__ lo)
{
    int i = blockIdx.x * blockDim.x + threadIdx.x;
    if (i >= MROWS * DT_RANK) return;
    int r = i >> 6, c = i & 63;
    float v = dbl[(size_t)r * DBL_W + c];
    __nv_bfloat16 h = __float2bfloat16(v);
    hi[i] = h;
    lo[i] = __float2bfloat16(v - __bfloat162float(h));
}

// ---------------- depthwise causal conv (k=4) + SiLU, float4, fused split ----------------
__global__ __launch_bounds__(256)
void conv_silu_v4(const float* __restrict__ xz, const float* __restrict__ w,
                  float* __restrict__ xc, __nv_bfloat16* __restrict__ xchi,
                  __nv_bfloat16* __restrict__ xclo)
{
    int v = blockIdx.x * blockDim.x + threadIdx.x;
    if (v >= MROWS * (D_INNER / 4)) return;
    int q = v & (D_INNER / 4 - 1);        // 0..511
    int row = v >> 9;
    int t = row & (SEQ - 1);
    int d4 = q * 4;

    float wr[4][4];
#pragma unroll
    for (int j = 0; j < 4; j++) {
        float4 wv = *(const float4*)(w + (d4 + j) * D_CONV);
        wr[j][0] = wv.x; wr[j][1] = wv.y; wr[j][2] = wv.z; wr[j][3] = wv.w;
    }

    float acc[4] = {0.f, 0.f, 0.f, 0.f};
#pragma unroll
    for (int k = 0; k < D_CONV; k++) {
        int tt = t - (D_CONV - 1) + k;
        if (tt >= 0) {
            float4 xv = *(const float4*)(xz + (size_t)(row - (D_CONV - 1) + k) * (2 * D_INNER) + d4);
            acc[0] = fmaf(wr[0][k], xv.x, acc[0]);
            acc[1] = fmaf(wr[1][k], xv.y, acc[1]);
            acc[2] = fmaf(wr[2][k], xv.z, acc[2]);
            acc[3] = fmaf(wr[3][k], xv.w, acc[3]);
        }
    }

    float o[4];
    __nv_bfloat16 h[4], l[4];
#pragma unroll
    for (int j = 0; j < 4; j++) {
        float s = acc[j];
        float sig = 1.f / (1.f + __expf(-s));
        o[j] = s * sig;
        h[j] = __float2bfloat16(o[j]);
        l[j] = __float2bfloat16(o[j] - __bfloat162float(h[j]));
    }
    size_t idx = (size_t)row * D_INNER + d4;
    *(float4*)(xc + idx) = make_float4(o[0], o[1], o[2], o[3]);
    __nv_bfloat162 hh0, hh1, ll0, ll1;
    hh0.x = h[0]; hh0.y = h[1]; hh1.x = h[2]; hh1.y = h[3];
    ll0.x = l[0]; ll0.y = l[1]; ll1.x = l[2]; ll1.y = l[3];
    *(__nv_bfloat162*)(xchi + idx)     = hh0;
    *(__nv_bfloat162*)(xchi + idx + 2) = hh1;
    *(__nv_bfloat162*)(xclo + idx)     = ll0;
    *(__nv_bfloat162*)(xclo + idx + 2) = ll1;
}

// ---------------- selective scan (coalesced, SMEM chunked) ----------------
#define SCHUNK 64
__global__ __launch_bounds__(256)
void scan_kernel(const float* __restrict__ dt, const float* __restrict__ xc,
                 const float* __restrict__ xz, const float* __restrict__ dblp,
                 const float* __restrict__ A_log, const float* __restrict__ Dp,
                 __nv_bfloat16* __restrict__ yhi, __nv_bfloat16* __restrict__ ylo)
{
    __shared__ float s_dt[SCHUNK][16];
    __shared__ float s_xc[SCHUNK][16];
    __shared__ float s_z[SCHUNK][16];
    __shared__ float s_B[SCHUNK][16];
    __shared__ float s_C[SCHUNK][16];
    __shared__ float s_y[SCHUNK][16];

    const int tid = threadIdx.x;
    const int g = tid >> 4;
    const int n = tid & 15;
    const int b = blockIdx.x >> 7;
    const int dblk = (blockIdx.x & 127) * 16;
    const int d = dblk + g;

    const float Aval = -expf(A_log[d * D_STATE + n]);
    const float Dval = Dp[d];

    float h = 0.f;
    for (int c = 0; c < SEQ / SCHUNK; c++) {
        const size_t rbase = (size_t)b * SEQ + c * SCHUNK;
        for (int idx = tid; idx < SCHUNK * 16; idx += 256) {
            int t = idx >> 4, j = idx & 15;
            size_t row = rbase + t;
            s_dt[t][j] = dt[row * D_INNER + dblk + j];
            s_xc[t][j] = xc[row * D_INNER + dblk + j];
            s_z[t][j]  = xz[row * (2 * D_INNER) + D_INNER + dblk + j];
            s_B[t][j]  = dblp[row * DBL_W + DT_RANK + j];
            s_C[t][j]  = dblp[row * DBL_W + DT_RANK + D_STATE + j];
        }
        __syncthreads();
#pragma unroll 4
        for (int t = 0; t < SCHUNK; t++) {
            float dtv = s_dt[t][g];
            float xv  = s_xc[t][g];
            float Bv  = s_B[t][n];
            float Cv  = s_C[t][n];
            h = fmaf(h, __expf(dtv * Aval), dtv * Bv * xv);
            float p = h * Cv;
            p += __shfl_xor_sync(0xffffffffu, p, 1);
            p += __shfl_xor_sync(0xffffffffu, p, 2);
            p += __shfl_xor_sync(0xffffffffu, p, 4);
            p += __shfl_xor_sync(0xffffffffu, p, 8);
            if (n == 0) s_y[t][g] = p + Dval * xv;
        }
        __syncthreads();
        for (int idx = tid; idx < SCHUNK * 16; idx += 256) {
            int t = idx >> 4, j = idx & 15;
            size_t row = rbase + t;
            float zv = s_z[t][j];
            float sig = 1.f / (1.f + __expf(-zv));
            float v = s_y[t][j] * (zv * sig);
            __nv_bfloat16 hv = __float2bfloat16(v);
            yhi[row * D_INNER + dblk + j] = hv;
            ylo[row * D_INNER + dblk + j] = __float2bfloat16(v - __bfloat162float(hv));
        }
        __syncthreads();
    }
}

// ---------------- launcher ----------------
extern "C" void kernel_launch(void* const* d_in, const int* in_sizes, int n_in,
                              void* d_out, int out_size)
{
    const float* x      = (const float*)d_in[0];
    const float* W_in   = (const float*)d_in[1];
    const float* conv_w = (const float*)d_in[2];
    const float* W_x    = (const float*)d_in[3];
    const float* W_dt   = (const float*)d_in[4];
    const float* b_dt   = (const float*)d_in[5];
    const float* A_log  = (const float*)d_in[6];
    const float* Dp     = (const float*)d_in[7];
    const float* W_out  = (const float*)d_in[8];
    float* out = (float*)d_out;

    float *xz, *xc, *dblp, *dtp;
    cudaGetSymbolAddress((void**)&xz, g_xz);
    cudaGetSymbolAddress((void**)&xc, g_xconv);
    cudaGetSymbolAddress((void**)&dblp, g_dbl);
    cudaGetSymbolAddress((void**)&dtp, g_dt);
    __nv_bfloat16 *xhi, *xlo, *wihi, *wilo, *yhi, *ylo, *wohi, *wolo;
    __nv_bfloat16 *xchi, *xclo, *wxhi, *wxlo, *d4hi, *d4lo, *wdthi, *wdtlo;
    cudaGetSymbolAddress((void**)&xhi, g_xhi);
    cudaGetSymbolAddress((void**)&xlo, g_xlo);
    cudaGetSymbolAddress((void**)&wihi, g_wihi);
    cudaGetSymbolAddress((void**)&wilo, g_wilo);
    cudaGetSymbolAddress((void**)&yhi, g_yhi);
    cudaGetSymbolAddress((void**)&ylo, g_ylo);
    cudaGetSymbolAddress((void**)&wohi, g_wohi);
    cudaGetSymbolAddress((void**)&wolo, g_wolo);
    cudaGetSymbolAddress((void**)&xchi, g_xchi);
    cudaGetSymbolAddress((void**)&xclo, g_xclo);
    cudaGetSymbolAddress((void**)&wxhi, g_wxhi);
    cudaGetSymbolAddress((void**)&wxlo, g_wxlo);
    cudaGetSymbolAddress((void**)&d4hi, g_d4hi);
    cudaGetSymbolAddress((void**)&d4lo, g_d4lo);
    cudaGetSymbolAddress((void**)&wdthi, g_wdthi);
    cudaGetSymbolAddress((void**)&wdtlo, g_wdtlo);

    cudaFuncSetAttribute(gemm_bf16x3_mma, cudaFuncAttributeMaxDynamicSharedMemorySize, MMA_SMEM);

    // splits for GEMM 1
    split_bf16<<<(MROWS * D_MODEL + 255) / 256, 256>>>(x, xhi, xlo, MROWS * D_MODEL);
    split_bf16<<<(2 * D_INNER * D_MODEL + 255) / 256, 256>>>(W_in, wihi, wilo, 2 * D_INNER * D_MODEL);

    // 1) xz = x @ W_in^T  (8192 x 4096, K=1024)
    gemm_bf16x3_mma<<<dim3(4096 / 128, MROWS / 128), 256, MMA_SMEM>>>(
        xhi, xlo, wihi, wilo, nullptr, xz,
        2 * D_INNER, D_MODEL, D_MODEL, D_MODEL, 2 * D_INNER, EP_NONE);

    // 2) depthwise causal conv + SiLU, fused bf16 split of x_conv
    conv_silu_v4<<<(MROWS * (D_INNER / 4) + 255) / 256, 256>>>(xz, conv_w, xc, xchi, xclo);

    // W_x split with zero-padding 96 -> 128 rows
    split_pad_bf16<<<(128 * D_INNER + 255) / 256, 256>>>(W_x, wxhi, wxlo, DBL_W, 128, D_INNER);

    // 3) dbl = x_conv @ W_x^T  (8192 x 96, K=2048)
    gemm_bf16x3_mma<<<dim3(1, MROWS / 128), 256, MMA_SMEM>>>(
        xchi, xclo, wxhi, wxlo, nullptr, dblp,
        DBL_W, D_INNER, D_INNER, D_INNER, DBL_W, EP_NONE);

    // splits for GEMM 4
    split_dbl64<<<(MROWS * DT_RANK + 255) / 256, 256>>>(dblp, d4hi, d4lo);
    split_bf16<<<(D_INNER * DT_RANK + 255) / 256, 256>>>(W_dt, wdthi, wdtlo, D_INNER * DT_RANK);

    // 4) dt = softplus(dbl[:, :64] @ W_dt^T + b_dt)  (8192 x 2048, K=64)
    gemm_bf16x3_mma<<<dim3(D_INNER / 128, MROWS / 128), 256, MMA_SMEM>>>(
        d4hi, d4lo, wdthi, wdtlo, b_dt, dtp,
        D_INNER, DT_RANK, DT_RANK, DT_RANK, D_INNER, EP_SOFTPLUS_BIAS);

    // 5) selective scan + skip + gating -> yhi/ylo (bf16 split fused)
    scan_kernel<<<BATCH * (D_INNER / 16), 256>>>(dtp, xc, xz, dblp, A_log, Dp, yhi, ylo);

    // split W_out
    split_bf16<<<(D_MODEL * D_INNER + 255) / 256, 256>>>(W_out, wohi, wolo, D_MODEL * D_INNER);

    // 6) out = y @ W_out^T  (8192 x 1024, K=2048)
    gemm_bf16x3_mma<<<dim3(D_MODEL / 128, MROWS / 128), 256, MMA_SMEM>>>(
        yhi, ylo, wohi, wolo, nullptr, out,
        D_MODEL, D_INNER, D_INNER, D_INNER, D_MODEL, EP_NONE);
}